// round 14
// baseline (speedup 1.0000x reference)
#include <cuda_runtime.h>
#include <cuda_fp16.h>
#include <cstdint>

#define BB 4
#define NN 2048
#define KK 32
#define CIN 16
#define COUT 32
#define HH 32
#define RTOT (BB*NN*KK)      // 262144
#define MTOT (BB*NN)         // 8192
#define EPS 1e-5f
#define FULLMASK 0xffffffffu

// Q layout: [m][jq=0..3][o] as uint4 (4 half2 = 8 j's). Coalesced per warp (lane=o).
#define QSTRIDE4 (4*32)

// dynamic smem layout for knn branch of knnq
#define SM_SP4   0
#define SM_RED   32768
#define SM_W1    34816
#define SM_B1    35200
#define SM_TOTAL 35328

// ---------------- scratch ----------------
__device__ __align__(16) float g_h2[(size_t)RTOT*HH];       // 32 MB (pre-BN2 h2)
__device__ __align__(16) uint4 g_Q4[(size_t)MTOT*QSTRIDE4]; // 16.8 MB fp16 Q tiles (UNscaled)
__device__ __align__(16) float g_Qb[(size_t)MTOT*COUT];     // 1 MB pb3 per (m,o)
__device__ __align__(16) float4 g_rel[RTOT];                // 4 MB rel coords
__device__ int g_idx[RTOT];
__device__ __align__(16) float g_ps [32*1024];
__device__ __align__(16) float g_ps2[32*1024];
__device__ float g_sc2[64];
__device__ __align__(16) float g_W2f[1024];   // sc1-folded W2
__device__ float g_b2f[32];                   // sh1-folded b2
__device__ float cW1x[32], cW1y[32], cW1z[32], cB1[32];

// ---------------- helpers ----------------
__device__ __forceinline__ unsigned long long pack2(float x, float y) {
    unsigned long long r;
    asm("mov.b64 %0, {%1,%2};" : "=l"(r) : "f"(x), "f"(y));
    return r;
}
__device__ __forceinline__ float2 unpack2(unsigned long long v) {
    float2 r;
    asm("mov.b64 {%0,%1}, %2;" : "=f"(r.x), "=f"(r.y) : "l"(v));
    return r;
}
__device__ __forceinline__ unsigned long long ffma2(unsigned long long a, unsigned long long b, unsigned long long c) {
    unsigned long long d;
    asm("fma.rn.f32x2 %0, %1, %2, %3;" : "=l"(d) : "l"(a), "l"(b), "l"(c));
    return d;
}

// warp transpose-reduce
__device__ __forceinline__ void tr32(float (&acc)[32], int lane) {
#pragma unroll
    for (int s = 16; s >= 1; s >>= 1) {
#pragma unroll
        for (int i = 0; i < s; i++) {
            float a0 = acc[i], a1 = acc[i + s];
            float give = (lane & s) ? a0 : a1;
            float keep = (lane & s) ? a1 : a0;
            acc[i] = keep + __shfl_xor_sync(FULLMASK, give, s);
        }
    }
}

// ---------------- KNN helpers ----------------
__device__ __forceinline__ void cas_pair(float& d, int& i, int stride, bool up, int lane) {
    float od = __shfl_xor_sync(FULLMASK, d, stride);
    int   oi = __shfl_xor_sync(FULLMASK, i, stride);
    bool otherSmaller = (od < d) || (od == d && oi < i);
    bool lower = ((lane & stride) == 0);
    bool take = (lower == up) ? otherSmaller : !otherSmaller;
    if (take) { d = od; i = oi; }
}
__device__ __forceinline__ void sort32(float& d, int& i, bool asc, int lane) {
#pragma unroll
    for (int k = 2; k <= 32; k <<= 1) {
        bool up = (((lane & k) == 0) == asc);
#pragma unroll
        for (int s = k >> 1; s > 0; s >>= 1) cas_pair(d, i, s, up, lane);
    }
}
__device__ __forceinline__ void merge32(float& d, int& i, int lane) {
#pragma unroll
    for (int s = 16; s > 0; s >>= 1) cas_pair(d, i, s, true, lane);
}

// ---------------- knnq: blocks [0,1024) = KNN+rel+h1stats; [1024,2048) = qcompute ----------------
__global__ __launch_bounds__(256) void knnq_kernel(const float* __restrict__ xyz,
                                                   const float* __restrict__ W1,
                                                   const float* __restrict__ b1,
                                                   const float* __restrict__ points,
                                                   const float* __restrict__ W3,
                                                   const float* __restrict__ b3) {
    extern __shared__ char smdyn[];
    int tid = threadIdx.x;

    if (blockIdx.x >= 1024) {
        // ================= qcompute branch (independent of knn) =================
        __shared__ float sp[8][16];
        int mg0 = (blockIdx.x - 1024) * 8;
        if (tid < 128) sp[tid >> 4][tid & 15] = points[(size_t)(mg0 + (tid >> 4)) * CIN + (tid & 15)];
        __syncthreads();

        int o = tid & 31, jg = tid >> 5, j0 = jg * 4;
        float acc[8][4];
#pragma unroll
        for (int m = 0; m < 8; m++)
#pragma unroll
            for (int jj = 0; jj < 4; jj++) acc[m][jj] = 0.f;

#pragma unroll
        for (int c = 0; c < 16; c++) {
            float w0 = __ldg(W3 + (size_t)(j0 + 0) * 512 + c * 32 + o);
            float w1 = __ldg(W3 + (size_t)(j0 + 1) * 512 + c * 32 + o);
            float w2 = __ldg(W3 + (size_t)(j0 + 2) * 512 + c * 32 + o);
            float w3 = __ldg(W3 + (size_t)(j0 + 3) * 512 + c * 32 + o);
#pragma unroll
            for (int m = 0; m < 8; m++) {
                float pm = sp[m][c];
                acc[m][0] = fmaf(pm, w0, acc[m][0]);
                acc[m][1] = fmaf(pm, w1, acc[m][1]);
                acc[m][2] = fmaf(pm, w2, acc[m][2]);
                acc[m][3] = fmaf(pm, w3, acc[m][3]);
            }
        }
        uint2* q2base = (uint2*)g_Q4;
#pragma unroll
        for (int m = 0; m < 8; m++) {
            __half2 p0 = __floats2half2_rn(acc[m][0], acc[m][1]);
            __half2 p1 = __floats2half2_rn(acc[m][2], acc[m][3]);
            uint2 u;
            u.x = *(const unsigned int*)&p0;
            u.y = *(const unsigned int*)&p1;
            size_t u2idx = (((size_t)(mg0 + m) * 4 + (jg >> 1)) * 32 + o) * 2 + (jg & 1);
            q2base[u2idx] = u;
        }
        {
            int m = tid >> 5;
            float pb = 0.f;
#pragma unroll
            for (int c = 0; c < 16; c++) pb = fmaf(sp[m][c], __ldg(b3 + c * 32 + o), pb);
            g_Qb[(size_t)(mg0 + m) * 32 + o] = pb;
        }
        return;
    }

    // ================= knn branch =================
    float4* sp4 = (float4*)(smdyn + SM_SP4);
    float (*red)[8][32] = (float(*)[8][32])(smdyn + SM_RED);
    float* sW1  = (float*)(smdyn + SM_W1);
    float* sb1s = (float*)(smdyn + SM_B1);

    int b = blockIdx.x >> 8;
    int nbase = (blockIdx.x & 255) * 8;
    if (tid < 96) sW1[tid] = W1[tid];
    else if (tid < 128) sb1s[tid - 96] = b1[tid - 96];
    for (int i = tid; i < NN; i += 256) {
        const float* p = xyz + ((size_t)b * NN + i) * 3;
        float x = p[0], y = p[1], z = p[2];
        sp4[i] = make_float4(x, y, z, x * x + y * y + z * z);
    }
    __syncthreads();
    int w = tid >> 5, lane = tid & 31;
    int n = nbase + w;
    float4 qp = sp4[n];

    // init: top-32 of first 64 candidates
    float4 tA = sp4[lane];
    float4 tB = sp4[32 + lane];
    float d = fmaf(-2.f, qp.x * tA.x + qp.y * tA.y + qp.z * tA.z, qp.w + tA.w);
    int di = lane;
    float e = fmaf(-2.f, qp.x * tB.x + qp.y * tB.y + qp.z * tB.z, qp.w + tB.w);
    int ei = 32 + lane;
    sort32(d, di, true, lane);
    sort32(e, ei, false, lane);
    bool takeE = (e < d) || (e == d && ei < di);
    if (takeE) { d = e; di = ei; }
    merge32(d, di, lane);
    float kmax = __shfl_sync(FULLMASK, d, 31);

    for (int c = 1; c < 32; c++) {
        int j = c * 64 + lane;
        float4 t0 = sp4[j];
        float4 t1 = sp4[j + 32];
        float cd0 = fmaf(-2.f, qp.x * t0.x + qp.y * t0.y + qp.z * t0.z, qp.w + t0.w);
        float cd1 = fmaf(-2.f, qp.x * t1.x + qp.y * t1.y + qp.z * t1.z, qp.w + t1.w);
        unsigned m0 = __ballot_sync(FULLMASK, cd0 < kmax);
        while (m0) {
            int src = __ffs(m0) - 1;
            m0 &= m0 - 1;
            float v = __shfl_sync(FULLMASK, cd0, src);
            if (v >= kmax) continue;
            int vi = j - lane + src;
            unsigned le = __ballot_sync(FULLMASK, d <= v);
            int pos = __popc(le);
            float ds = __shfl_up_sync(FULLMASK, d, 1);
            int   is = __shfl_up_sync(FULLMASK, di, 1);
            if (lane == pos)      { d = v;  di = vi; }
            else if (lane > pos)  { d = ds; di = is; }
            kmax = __shfl_sync(FULLMASK, d, 31);
        }
        unsigned m1 = __ballot_sync(FULLMASK, cd1 < kmax);
        while (m1) {
            int src = __ffs(m1) - 1;
            m1 &= m1 - 1;
            float v = __shfl_sync(FULLMASK, cd1, src);
            if (v >= kmax) continue;
            int vi = j - lane + 32 + src;
            unsigned le = __ballot_sync(FULLMASK, d <= v);
            int pos = __popc(le);
            float ds = __shfl_up_sync(FULLMASK, d, 1);
            int   is = __shfl_up_sync(FULLMASK, di, 1);
            if (lane == pos)      { d = v;  di = vi; }
            else if (lane > pos)  { d = ds; di = is; }
            kmax = __shfl_sync(FULLMASK, d, 31);
        }
    }
    size_t r = ((size_t)b * NN + n) * KK + lane;
    g_idx[r] = di;

    float4 tn = sp4[di];
    float rx = tn.x - qp.x, ry = tn.y - qp.y, rz = tn.z - qp.z;
    g_rel[r] = make_float4(rx, ry, rz, 0.f);

    float s[32];
#pragma unroll
    for (int c = 0; c < 32; c++)
        s[c] = fmaxf(fmaf(rx, sW1[c], fmaf(ry, sW1[32 + c], fmaf(rz, sW1[64 + c], sb1s[c]))), 0.f);
    tr32(s, lane);
    red[0][w][lane] = s[0];
    float s2[32];
#pragma unroll
    for (int c = 0; c < 32; c++) {
        float v = fmaxf(fmaf(rx, sW1[c], fmaf(ry, sW1[32 + c], fmaf(rz, sW1[64 + c], sb1s[c]))), 0.f);
        s2[c] = v * v;
    }
    tr32(s2, lane);
    red[1][w][lane] = s2[0];
    __syncthreads();
    if (tid < 32) {
        float a = 0.f, a2 = 0.f;
#pragma unroll
        for (int ww = 0; ww < 8; ww++) { a += red[0][ww][tid]; a2 += red[1][ww][tid]; }
        g_ps [tid * 1024 + blockIdx.x] = a;
        g_ps2[tid * 1024 + blockIdx.x] = a2;
    }
}

// ---------------- fin1 (+prep): BN1 folded into W2f/b2f ----------------
__global__ __launch_bounds__(1024) void fin1_kernel(const float* __restrict__ g1,
                                                    const float* __restrict__ be1,
                                                    const float* __restrict__ W2,
                                                    const float* __restrict__ b2,
                                                    const float* __restrict__ W1,
                                                    const float* __restrict__ b1) {
    __shared__ float ssc[32], ssh[32];
    int tid = threadIdx.x, w = tid >> 5, l = tid & 31;
    if (tid < 32) { cW1x[tid] = W1[tid]; cW1y[tid] = W1[32 + tid]; cW1z[tid] = W1[64 + tid]; cB1[tid] = b1[tid]; }
    const float4* P  = (const float4*)(g_ps  + w * 1024);
    const float4* P2 = (const float4*)(g_ps2 + w * 1024);
    float s = 0.f, s2 = 0.f;
#pragma unroll
    for (int it = 0; it < 8; it++) {
        float4 a = P[it * 32 + l];
        float4 c = P2[it * 32 + l];
        s  += (a.x + a.y) + (a.z + a.w);
        s2 += (c.x + c.y) + (c.z + c.w);
    }
#pragma unroll
    for (int o = 16; o >= 1; o >>= 1) {
        s  += __shfl_down_sync(FULLMASK, s, o);
        s2 += __shfl_down_sync(FULLMASK, s2, o);
    }
    if (l == 0) {
        const float invc = 1.f / (float)RTOT;
        float mean = s * invc;
        float var  = s2 * invc - mean * mean;
        float iv = rsqrtf(var + EPS);
        float sc = g1[w] * iv;
        ssc[w] = sc;
        ssh[w] = fmaf(-mean, sc, be1[w]);
    }
    __syncthreads();
    g_W2f[tid] = ssc[tid >> 5] * W2[tid];
    float v = ssh[l] * W2[l * 32 + w];
#pragma unroll
    for (int o = 16; o >= 1; o >>= 1) v += __shfl_down_sync(FULLMASK, v, o);
    if (l == 0) g_b2f[w] = b2[w] + v;
}

// ---------------- fin2: partials -> sc2 ----------------
__global__ __launch_bounds__(1024) void fin_kernel(int G, float invc,
                                                   const float* __restrict__ gamma,
                                                   const float* __restrict__ beta,
                                                   float* __restrict__ scsh) {
    int tid = threadIdx.x, w = tid >> 5, l = tid & 31;
    const float4* P  = (const float4*)(g_ps  + w * G);
    const float4* P2 = (const float4*)(g_ps2 + w * G);
    float s = 0.f, s2 = 0.f;
#pragma unroll 4
    for (int i = l; i < (G >> 2); i += 32) {
        float4 a = P[i];
        float4 c = P2[i];
        s  += (a.x + a.y) + (a.z + a.w);
        s2 += (c.x + c.y) + (c.z + c.w);
    }
#pragma unroll
    for (int o = 16; o >= 1; o >>= 1) {
        s  += __shfl_down_sync(FULLMASK, s, o);
        s2 += __shfl_down_sync(FULLMASK, s2, o);
    }
    if (l == 0) {
        float mean = s * invc;
        float var  = s2 * invc - mean * mean;
        float iv = rsqrtf(var + EPS);
        float sc = gamma[w] * iv;
        scsh[w]      = sc;
        scsh[32 + w] = fmaf(-mean, sc, beta[w]);
    }
}

// ---------------- stage2: 2 rows/thread; W2 rows via LDS.128 ----------------
__global__ __launch_bounds__(256) void stage2_kernel() {
    __shared__ __align__(16) float sW2f[1024];
    __shared__ float sb2f[32];
    __shared__ float sW1x[32], sW1y[32], sW1z[32], sB1[32];
    __shared__ float red[2][8][32];
    int tid = threadIdx.x;
    ((float4*)sW2f)[tid] = ((const float4*)g_W2f)[tid & 255];
    if (tid < 32) {
        sb2f[tid] = g_b2f[tid];
        sW1x[tid] = cW1x[tid]; sW1y[tid] = cW1y[tid];
        sW1z[tid] = cW1z[tid]; sB1[tid]  = cB1[tid];
    }
    __syncthreads();

    int rA = blockIdx.x * 256 + tid;
    int rB = rA + 131072;
    float4 relA = g_rel[rA];
    float4 relB = g_rel[rB];

    unsigned long long accA[16], accB[16];
#pragma unroll
    for (int q = 0; q < 16; q++) {
        unsigned long long bb = pack2(sb2f[2 * q], sb2f[2 * q + 1]);
        accA[q] = bb; accB[q] = bb;
    }
    const ulonglong2* w2p = (const ulonglong2*)sW2f;
#pragma unroll
    for (int j = 0; j < 32; j++) {
        float hA = fmaxf(fmaf(relA.x, sW1x[j], fmaf(relA.y, sW1y[j], fmaf(relA.z, sW1z[j], sB1[j]))), 0.f);
        float hB = fmaxf(fmaf(relB.x, sW1x[j], fmaf(relB.y, sW1y[j], fmaf(relB.z, sW1z[j], sB1[j]))), 0.f);
        unsigned long long hvA = pack2(hA, hA);
        unsigned long long hvB = pack2(hB, hB);
        const ulonglong2* row = w2p + j * 8;
#pragma unroll
        for (int q = 0; q < 8; q++) {
            ulonglong2 wv = row[q];
            accA[2 * q]     = ffma2(hvA, wv.x, accA[2 * q]);
            accA[2 * q + 1] = ffma2(hvA, wv.y, accA[2 * q + 1]);
            accB[2 * q]     = ffma2(hvB, wv.x, accB[2 * q]);
            accB[2 * q + 1] = ffma2(hvB, wv.y, accB[2 * q + 1]);
        }
    }

    float vA[32], vB[32];
#pragma unroll
    for (int q = 0; q < 16; q++) {
        float2 pA = unpack2(accA[q]);
        float2 pB = unpack2(accB[q]);
        vA[2 * q] = fmaxf(pA.x, 0.f); vA[2 * q + 1] = fmaxf(pA.y, 0.f);
        vB[2 * q] = fmaxf(pB.x, 0.f); vB[2 * q + 1] = fmaxf(pB.y, 0.f);
    }
    float4* oA = (float4*)(g_h2 + (size_t)rA * 32);
    float4* oB = (float4*)(g_h2 + (size_t)rB * 32);
#pragma unroll
    for (int q = 0; q < 8; q++) {
        oA[q] = make_float4(vA[4 * q], vA[4 * q + 1], vA[4 * q + 2], vA[4 * q + 3]);
        oB[q] = make_float4(vB[4 * q], vB[4 * q + 1], vB[4 * q + 2], vB[4 * q + 3]);
    }

    float s[32], s2[32];
#pragma unroll
    for (int c = 0; c < 32; c++) {
        s[c]  = vA[c] + vB[c];
        s2[c] = fmaf(vA[c], vA[c], vB[c] * vB[c]);
    }
    int lane = tid & 31, w = tid >> 5;
    tr32(s, lane); tr32(s2, lane);
    red[0][w][lane] = s[0]; red[1][w][lane] = s2[0];
    __syncthreads();
    if (tid < 32) {
        float a = 0.f, a2 = 0.f;
#pragma unroll
        for (int ww = 0; ww < 8; ww++) { a += red[0][ww][tid]; a2 += red[1][ww][tid]; }
        g_ps [tid * 512 + blockIdx.x] = a;
        g_ps2[tid * 512 + blockIdx.x] = a2;
    }
}

// ---------------- stage3: BN2 applied on sH load; Q unscaled fp16 ----------------
__global__ __launch_bounds__(256) void stage3_kernel(float* __restrict__ out) {
    __shared__ float2 sH[32 * 16];
    __shared__ int sidx[32];
    __shared__ float wmax[8][32];
    __shared__ float sbn[64];
    int tid = threadIdx.x;
    int q = blockIdx.x;
    size_t r0 = (size_t)q * KK;
    if (tid < 32) sidx[tid] = g_idx[r0 + tid];
    else if (tid >= 64 && tid < 128) sbn[tid - 64] = g_sc2[tid - 64];
    __syncthreads();
    for (int t = tid; t < 512; t += 256) {
        int k = t >> 4, jp = t & 15;
        float2 h = ((const float2*)(g_h2 + (r0 + k) * 32))[jp];
        int j = jp * 2;
        sH[k * 16 + jp] = make_float2(fmaf(h.x, sbn[j],     sbn[32 + j]),
                                      fmaf(h.y, sbn[j + 1], sbn[33 + j]));
    }
    __syncthreads();

    int w = tid >> 5, o = tid & 31, b = q >> 11;
    float vmax = -3.4e38f;
#pragma unroll
    for (int kk = 0; kk < 4; kk++) {
        int k = w + kk * 8;
        int m = sidx[k];
        size_t mg = ((size_t)(b << 11) + m);
        const uint4* Qp = g_Q4 + mg * QSTRIDE4 + o;
        const float2* sHk = &sH[k * 16];
        float acc = __ldg(g_Qb + mg * 32 + o);
#pragma unroll
        for (int jq = 0; jq < 4; jq++) {
            uint4 u = Qp[(size_t)jq * 32];
            float2 q0 = __half22float2(*(const __half2*)&u.x);
            float2 q1 = __half22float2(*(const __half2*)&u.y);
            float2 q2 = __half22float2(*(const __half2*)&u.z);
            float2 q3 = __half22float2(*(const __half2*)&u.w);
            float2 h0 = sHk[jq * 4 + 0], h1 = sHk[jq * 4 + 1];
            float2 h2 = sHk[jq * 4 + 2], h3 = sHk[jq * 4 + 3];
            acc = fmaf(h0.x, q0.x, fmaf(h0.y, q0.y, acc));
            acc = fmaf(h1.x, q1.x, fmaf(h1.y, q1.y, acc));
            acc = fmaf(h2.x, q2.x, fmaf(h2.y, q2.y, acc));
            acc = fmaf(h3.x, q3.x, fmaf(h3.y, q3.y, acc));
        }
        vmax = fmaxf(vmax, acc);
    }
    wmax[w][o] = vmax;
    __syncthreads();
    if (tid < 32) {
        float v = wmax[0][tid];
#pragma unroll
        for (int i = 1; i < 8; i++) v = fmaxf(v, wmax[i][tid]);
        out[(size_t)q * 32 + tid] = v;
    }
}

// ---------------- statsC ----------------
__global__ __launch_bounds__(256) void statsC_kernel(const float* __restrict__ out) {
    int tid = threadIdx.x;
    int q = blockIdx.x * 256 + tid;
    float v[32], s2[32];
    const float4* p = (const float4*)(out + (size_t)q * 32);
#pragma unroll
    for (int i = 0; i < 8; i++) {
        float4 x = p[i];
        v[4 * i] = x.x; v[4 * i + 1] = x.y; v[4 * i + 2] = x.z; v[4 * i + 3] = x.w;
    }
#pragma unroll
    for (int c = 0; c < 32; c++) s2[c] = v[c] * v[c];
    int lane = tid & 31, w = tid >> 5;
    tr32(v, lane); tr32(s2, lane);
    __shared__ float red[2][8][32];
    red[0][w][lane] = v[0]; red[1][w][lane] = s2[0];
    __syncthreads();
    if (tid < 32) {
        float a = 0.f, a2 = 0.f;
#pragma unroll
        for (int ww = 0; ww < 8; ww++) { a += red[0][ww][tid]; a2 += red[1][ww][tid]; }
        g_ps [tid * 32 + blockIdx.x] = a;
        g_ps2[tid * 32 + blockIdx.x] = a2;
    }
}

// ---------------- finalbn: fused fin3 + normalize ----------------
__global__ __launch_bounds__(256) void finalbn_kernel(float* __restrict__ out,
                                                      const float* __restrict__ gbn,
                                                      const float* __restrict__ bbn) {
    __shared__ float ssc[32], ssh[32];
    int tid = threadIdx.x;
    if (tid < 32) {
        float s = 0.f, s2 = 0.f;
#pragma unroll
        for (int i = 0; i < 32; i++) {
            s  += g_ps [tid * 32 + i];
            s2 += g_ps2[tid * 32 + i];
        }
        const float invc = 1.f / (float)MTOT;
        float mean = s * invc;
        float var  = s2 * invc - mean * mean;
        float iv = rsqrtf(var + EPS);
        float sc = gbn[tid] * iv;
        ssc[tid] = sc;
        ssh[tid] = fmaf(-mean, sc, bbn[tid]);
    }
    __syncthreads();
    int e = blockIdx.x * 256 + tid;
    float4 v = ((float4*)out)[e];
    int c = (e * 4) & 31;
    v.x = fmaf(v.x, ssc[c],     ssh[c]);
    v.y = fmaf(v.y, ssc[c + 1], ssh[c + 1]);
    v.z = fmaf(v.z, ssc[c + 2], ssh[c + 2]);
    v.w = fmaf(v.w, ssc[c + 3], ssh[c + 3]);
    ((float4*)out)[e] = v;
}

// ---------------- launcher ----------------
extern "C" void kernel_launch(void* const* d_in, const int* in_sizes, int n_in,
                              void* d_out, int out_size) {
    const float* xyz    = (const float*)d_in[0];
    const float* points = (const float*)d_in[1];
    const float* W1     = (const float*)d_in[2];
    const float* b1     = (const float*)d_in[3];
    const float* g1     = (const float*)d_in[4];
    const float* be1    = (const float*)d_in[5];
    const float* W2     = (const float*)d_in[6];
    const float* b2     = (const float*)d_in[7];
    const float* g2     = (const float*)d_in[8];
    const float* be2    = (const float*)d_in[9];
    const float* W3     = (const float*)d_in[10];
    const float* b3     = (const float*)d_in[11];
    const float* gbn    = (const float*)d_in[12];
    const float* bbn    = (const float*)d_in[13];
    float* out = (float*)d_out;

    float* p_sc2; cudaGetSymbolAddress((void**)&p_sc2, g_sc2);

    knnq_kernel   <<<2048, 256, SM_TOTAL>>>(xyz, W1, b1, points, W3, b3);
    fin1_kernel   <<<1, 1024>>>(g1, be1, W2, b2, W1, b1);
    stage2_kernel <<<512, 256>>>();
    fin_kernel    <<<1, 1024>>>(512, 1.f / (float)RTOT, g2, be2, p_sc2);
    stage3_kernel <<<MTOT, 256>>>(out);
    statsC_kernel <<<32, 256>>>(out);
    finalbn_kernel<<<256, 256>>>(out, gbn, bbn);
}

// round 15
// speedup vs baseline: 1.0885x; 1.0885x over previous
#include <cuda_runtime.h>
#include <cuda_fp16.h>
#include <cstdint>

#define BB 4
#define NN 2048
#define KK 32
#define CIN 16
#define COUT 32
#define HH 32
#define RTOT (BB*NN*KK)      // 262144
#define MTOT (BB*NN)         // 8192
#define EPS 1e-5f
#define FULLMASK 0xffffffffu

// Q layout: [m][jq=0..3][o] as uint4 (4 half2 = 8 j's). Coalesced per warp (lane=o).
#define QSTRIDE4 (4*32)

// ---------------- scratch ----------------
__device__ __align__(16) float g_h2[(size_t)RTOT*HH];       // 32 MB (pre-BN2 h2)
__device__ __align__(16) uint4 g_Q4[(size_t)MTOT*QSTRIDE4]; // 16.8 MB fp16 Q tiles
__device__ __align__(16) float g_Qb[(size_t)MTOT*COUT];     // 1 MB bias per (m,o)
__device__ __align__(16) float4 g_rel[RTOT];                // 4 MB rel coords
__device__ int g_idx[RTOT];
__device__ __align__(16) float g_ps [32*1024];
__device__ __align__(16) float g_ps2[32*1024];
__device__ float g_sc2[64];
__device__ __align__(16) float g_W2f[1024];   // sc1-folded W2
__device__ float g_b2f[32];                   // sh1-folded b2
__device__ float cW1x[32], cW1y[32], cW1z[32], cB1[32];

// ---------------- helpers ----------------
__device__ __forceinline__ unsigned long long pack2(float x, float y) {
    unsigned long long r;
    asm("mov.b64 %0, {%1,%2};" : "=l"(r) : "f"(x), "f"(y));
    return r;
}
__device__ __forceinline__ float2 unpack2(unsigned long long v) {
    float2 r;
    asm("mov.b64 {%0,%1}, %2;" : "=f"(r.x), "=f"(r.y) : "l"(v));
    return r;
}
__device__ __forceinline__ unsigned long long ffma2(unsigned long long a, unsigned long long b, unsigned long long c) {
    unsigned long long d;
    asm("fma.rn.f32x2 %0, %1, %2, %3;" : "=l"(d) : "l"(a), "l"(b), "l"(c));
    return d;
}

// warp transpose-reduce
__device__ __forceinline__ void tr32(float (&acc)[32], int lane) {
#pragma unroll
    for (int s = 16; s >= 1; s >>= 1) {
#pragma unroll
        for (int i = 0; i < s; i++) {
            float a0 = acc[i], a1 = acc[i + s];
            float give = (lane & s) ? a0 : a1;
            float keep = (lane & s) ? a1 : a0;
            acc[i] = keep + __shfl_xor_sync(FULLMASK, give, s);
        }
    }
}

// ---------------- KNN + rel + h1 stats ----------------
__device__ __forceinline__ void cas_pair(float& d, int& i, int stride, bool up, int lane) {
    float od = __shfl_xor_sync(FULLMASK, d, stride);
    int   oi = __shfl_xor_sync(FULLMASK, i, stride);
    bool otherSmaller = (od < d) || (od == d && oi < i);
    bool lower = ((lane & stride) == 0);
    bool take = (lower == up) ? otherSmaller : !otherSmaller;
    if (take) { d = od; i = oi; }
}
__device__ __forceinline__ void sort32(float& d, int& i, bool asc, int lane) {
#pragma unroll
    for (int k = 2; k <= 32; k <<= 1) {
        bool up = (((lane & k) == 0) == asc);
#pragma unroll
        for (int s = k >> 1; s > 0; s >>= 1) cas_pair(d, i, s, up, lane);
    }
}
__device__ __forceinline__ void merge32(float& d, int& i, int lane) {
#pragma unroll
    for (int s = 16; s > 0; s >>= 1) cas_pair(d, i, s, true, lane);
}

__global__ __launch_bounds__(256) void knn_kernel(const float* __restrict__ xyz,
                                                  const float* __restrict__ W1,
                                                  const float* __restrict__ b1) {
    __shared__ float4 sp4[NN];
    __shared__ float red[2][8][32];
    __shared__ float sW1[96], sb1s[32];
    int b = blockIdx.x >> 8;
    int nbase = (blockIdx.x & 255) * 8;
    int tid = threadIdx.x;
    if (tid < 96) sW1[tid] = W1[tid];
    else if (tid < 128) sb1s[tid - 96] = b1[tid - 96];
    for (int i = tid; i < NN; i += 256) {
        const float* p = xyz + ((size_t)b * NN + i) * 3;
        float x = p[0], y = p[1], z = p[2];
        sp4[i] = make_float4(x, y, z, x * x + y * y + z * z);
    }
    __syncthreads();
    int w = tid >> 5, lane = tid & 31;
    int n = nbase + w;
    float4 qp = sp4[n];

    // init: top-32 of first 64 candidates
    float4 tA = sp4[lane];
    float4 tB = sp4[32 + lane];
    float d = fmaf(-2.f, qp.x * tA.x + qp.y * tA.y + qp.z * tA.z, qp.w + tA.w);
    int di = lane;
    float e = fmaf(-2.f, qp.x * tB.x + qp.y * tB.y + qp.z * tB.z, qp.w + tB.w);
    int ei = 32 + lane;
    sort32(d, di, true, lane);
    sort32(e, ei, false, lane);
    bool takeE = (e < d) || (e == d && ei < di);
    if (takeE) { d = e; di = ei; }
    merge32(d, di, lane);
    float kmax = __shfl_sync(FULLMASK, d, 31);

    // 31 rounds of 64 candidates (covers 64..2047)
    for (int c = 1; c < 32; c++) {
        int j = c * 64 + lane;
        float4 t0 = sp4[j];
        float4 t1 = sp4[j + 32];
        float cd0 = fmaf(-2.f, qp.x * t0.x + qp.y * t0.y + qp.z * t0.z, qp.w + t0.w);
        float cd1 = fmaf(-2.f, qp.x * t1.x + qp.y * t1.y + qp.z * t1.z, qp.w + t1.w);
        unsigned m0 = __ballot_sync(FULLMASK, cd0 < kmax);
        while (m0) {
            int src = __ffs(m0) - 1;
            m0 &= m0 - 1;
            float v = __shfl_sync(FULLMASK, cd0, src);
            if (v >= kmax) continue;
            int vi = j - lane + src;
            unsigned le = __ballot_sync(FULLMASK, d <= v);
            int pos = __popc(le);
            float ds = __shfl_up_sync(FULLMASK, d, 1);
            int   is = __shfl_up_sync(FULLMASK, di, 1);
            if (lane == pos)      { d = v;  di = vi; }
            else if (lane > pos)  { d = ds; di = is; }
            kmax = __shfl_sync(FULLMASK, d, 31);
        }
        unsigned m1 = __ballot_sync(FULLMASK, cd1 < kmax);
        while (m1) {
            int src = __ffs(m1) - 1;
            m1 &= m1 - 1;
            float v = __shfl_sync(FULLMASK, cd1, src);
            if (v >= kmax) continue;
            int vi = j - lane + 32 + src;
            unsigned le = __ballot_sync(FULLMASK, d <= v);
            int pos = __popc(le);
            float ds = __shfl_up_sync(FULLMASK, d, 1);
            int   is = __shfl_up_sync(FULLMASK, di, 1);
            if (lane == pos)      { d = v;  di = vi; }
            else if (lane > pos)  { d = ds; di = is; }
            kmax = __shfl_sync(FULLMASK, d, 31);
        }
    }
    size_t r = ((size_t)b * NN + n) * KK + lane;
    g_idx[r] = di;

    float4 tn = sp4[di];
    float rx = tn.x - qp.x, ry = tn.y - qp.y, rz = tn.z - qp.z;
    g_rel[r] = make_float4(rx, ry, rz, 0.f);

    float s[32];
#pragma unroll
    for (int c = 0; c < 32; c++)
        s[c] = fmaxf(fmaf(rx, sW1[c], fmaf(ry, sW1[32 + c], fmaf(rz, sW1[64 + c], sb1s[c]))), 0.f);
    tr32(s, lane);
    red[0][w][lane] = s[0];
    float s2[32];
#pragma unroll
    for (int c = 0; c < 32; c++) {
        float v = fmaxf(fmaf(rx, sW1[c], fmaf(ry, sW1[32 + c], fmaf(rz, sW1[64 + c], sb1s[c]))), 0.f);
        s2[c] = v * v;
    }
    tr32(s2, lane);
    red[1][w][lane] = s2[0];
    __syncthreads();
    if (tid < 32) {
        float a = 0.f, a2 = 0.f;
#pragma unroll
        for (int ww = 0; ww < 8; ww++) { a += red[0][ww][tid]; a2 += red[1][ww][tid]; }
        g_ps [tid * 1024 + blockIdx.x] = a;
        g_ps2[tid * 1024 + blockIdx.x] = a2;
    }
}

// ---------------- fin1 (+prep): BN1 folded into W2f/b2f ----------------
__global__ __launch_bounds__(1024) void fin1_kernel(const float* __restrict__ g1,
                                                    const float* __restrict__ be1,
                                                    const float* __restrict__ W2,
                                                    const float* __restrict__ b2,
                                                    const float* __restrict__ W1,
                                                    const float* __restrict__ b1) {
    __shared__ float ssc[32], ssh[32];
    int tid = threadIdx.x, w = tid >> 5, l = tid & 31;
    if (tid < 32) { cW1x[tid] = W1[tid]; cW1y[tid] = W1[32 + tid]; cW1z[tid] = W1[64 + tid]; cB1[tid] = b1[tid]; }
    const float4* P  = (const float4*)(g_ps  + w * 1024);
    const float4* P2 = (const float4*)(g_ps2 + w * 1024);
    float s = 0.f, s2 = 0.f;
#pragma unroll
    for (int it = 0; it < 8; it++) {
        float4 a = P[it * 32 + l];
        float4 c = P2[it * 32 + l];
        s  += (a.x + a.y) + (a.z + a.w);
        s2 += (c.x + c.y) + (c.z + c.w);
    }
#pragma unroll
    for (int o = 16; o >= 1; o >>= 1) {
        s  += __shfl_down_sync(FULLMASK, s, o);
        s2 += __shfl_down_sync(FULLMASK, s2, o);
    }
    if (l == 0) {
        const float invc = 1.f / (float)RTOT;
        float mean = s * invc;
        float var  = s2 * invc - mean * mean;
        float iv = rsqrtf(var + EPS);
        float sc = g1[w] * iv;
        ssc[w] = sc;
        ssh[w] = fmaf(-mean, sc, be1[w]);
    }
    __syncthreads();
    g_W2f[tid] = ssc[tid >> 5] * W2[tid];
    float v = ssh[l] * W2[l * 32 + w];
#pragma unroll
    for (int o = 16; o >= 1; o >>= 1) v += __shfl_down_sync(FULLMASK, v, o);
    if (l == 0) g_b2f[w] = b2[w] + v;
}

// ---------------- fin2: partials -> sc2 ----------------
__global__ __launch_bounds__(1024) void fin_kernel(int G, float invc,
                                                   const float* __restrict__ gamma,
                                                   const float* __restrict__ beta,
                                                   float* __restrict__ scsh) {
    int tid = threadIdx.x, w = tid >> 5, l = tid & 31;
    const float4* P  = (const float4*)(g_ps  + w * G);
    const float4* P2 = (const float4*)(g_ps2 + w * G);
    float s = 0.f, s2 = 0.f;
#pragma unroll 4
    for (int i = l; i < (G >> 2); i += 32) {
        float4 a = P[i];
        float4 c = P2[i];
        s  += (a.x + a.y) + (a.z + a.w);
        s2 += (c.x + c.y) + (c.z + c.w);
    }
#pragma unroll
    for (int o = 16; o >= 1; o >>= 1) {
        s  += __shfl_down_sync(FULLMASK, s, o);
        s2 += __shfl_down_sync(FULLMASK, s2, o);
    }
    if (l == 0) {
        float mean = s * invc;
        float var  = s2 * invc - mean * mean;
        float iv = rsqrtf(var + EPS);
        float sc = gamma[w] * iv;
        scsh[w]      = sc;
        scsh[32 + w] = fmaf(-mean, sc, beta[w]);
    }
}

// ---------------- stage2: 2 rows/thread; W2 rows via LDS.128 ----------------
__global__ __launch_bounds__(256) void stage2_kernel() {
    __shared__ __align__(16) float sW2f[1024];
    __shared__ float sb2f[32];
    __shared__ float sW1x[32], sW1y[32], sW1z[32], sB1[32];
    __shared__ float red[2][8][32];
    int tid = threadIdx.x;
    ((float4*)sW2f)[tid] = ((const float4*)g_W2f)[tid & 255];
    if (tid < 32) {
        sb2f[tid] = g_b2f[tid];
        sW1x[tid] = cW1x[tid]; sW1y[tid] = cW1y[tid];
        sW1z[tid] = cW1z[tid]; sB1[tid]  = cB1[tid];
    }
    __syncthreads();

    int rA = blockIdx.x * 256 + tid;
    int rB = rA + 131072;
    float4 relA = g_rel[rA];
    float4 relB = g_rel[rB];

    unsigned long long accA[16], accB[16];
#pragma unroll
    for (int q = 0; q < 16; q++) {
        unsigned long long bb = pack2(sb2f[2 * q], sb2f[2 * q + 1]);
        accA[q] = bb; accB[q] = bb;
    }
    const ulonglong2* w2p = (const ulonglong2*)sW2f;
#pragma unroll
    for (int j = 0; j < 32; j++) {
        float hA = fmaxf(fmaf(relA.x, sW1x[j], fmaf(relA.y, sW1y[j], fmaf(relA.z, sW1z[j], sB1[j]))), 0.f);
        float hB = fmaxf(fmaf(relB.x, sW1x[j], fmaf(relB.y, sW1y[j], fmaf(relB.z, sW1z[j], sB1[j]))), 0.f);
        unsigned long long hvA = pack2(hA, hA);
        unsigned long long hvB = pack2(hB, hB);
        const ulonglong2* row = w2p + j * 8;
#pragma unroll
        for (int q = 0; q < 8; q++) {
            ulonglong2 wv = row[q];
            accA[2 * q]     = ffma2(hvA, wv.x, accA[2 * q]);
            accA[2 * q + 1] = ffma2(hvA, wv.y, accA[2 * q + 1]);
            accB[2 * q]     = ffma2(hvB, wv.x, accB[2 * q]);
            accB[2 * q + 1] = ffma2(hvB, wv.y, accB[2 * q + 1]);
        }
    }

    float vA[32], vB[32];
#pragma unroll
    for (int q = 0; q < 16; q++) {
        float2 pA = unpack2(accA[q]);
        float2 pB = unpack2(accB[q]);
        vA[2 * q] = fmaxf(pA.x, 0.f); vA[2 * q + 1] = fmaxf(pA.y, 0.f);
        vB[2 * q] = fmaxf(pB.x, 0.f); vB[2 * q + 1] = fmaxf(pB.y, 0.f);
    }
    float4* oA = (float4*)(g_h2 + (size_t)rA * 32);
    float4* oB = (float4*)(g_h2 + (size_t)rB * 32);
#pragma unroll
    for (int q = 0; q < 8; q++) {
        oA[q] = make_float4(vA[4 * q], vA[4 * q + 1], vA[4 * q + 2], vA[4 * q + 3]);
        oB[q] = make_float4(vB[4 * q], vB[4 * q + 1], vB[4 * q + 2], vB[4 * q + 3]);
    }

    float s[32], s2[32];
#pragma unroll
    for (int c = 0; c < 32; c++) {
        s[c]  = vA[c] + vB[c];
        s2[c] = fmaf(vA[c], vA[c], vB[c] * vB[c]);
    }
    int lane = tid & 31, w = tid >> 5;
    tr32(s, lane); tr32(s2, lane);
    red[0][w][lane] = s[0]; red[1][w][lane] = s2[0];
    __syncthreads();
    if (tid < 32) {
        float a = 0.f, a2 = 0.f;
#pragma unroll
        for (int ww = 0; ww < 8; ww++) { a += red[0][ww][tid]; a2 += red[1][ww][tid]; }
        g_ps [tid * 512 + blockIdx.x] = a;
        g_ps2[tid * 512 + blockIdx.x] = a2;
    }
}

// ---------------- qcompute: Q4[m][jq][o] uint4 (sc2-folded) + fp32 bias ----------------
__global__ __launch_bounds__(256) void qcompute_kernel(const float* __restrict__ points,
                                                       const float* __restrict__ W3,
                                                       const float* __restrict__ b3) {
    __shared__ float sp[8][16];
    __shared__ float ssc[32], ssh[32];
    __shared__ float r16p[8][8][32];   // [jg][m][o]
    int tid = threadIdx.x;
    int mg0 = blockIdx.x * 8;
    if (tid < 128) sp[tid >> 4][tid & 15] = points[(size_t)(mg0 + (tid >> 4)) * CIN + (tid & 15)];
    else if (tid < 160) { ssc[tid - 128] = g_sc2[tid - 128]; ssh[tid - 128] = g_sc2[32 + tid - 128]; }
    __syncthreads();

    int o = tid & 31, jg = tid >> 5, j0 = jg * 4;
    float acc[8][4];
#pragma unroll
    for (int m = 0; m < 8; m++)
#pragma unroll
        for (int jj = 0; jj < 4; jj++) acc[m][jj] = 0.f;

#pragma unroll
    for (int c = 0; c < 16; c++) {
        float w0 = __ldg(W3 + (size_t)(j0 + 0) * 512 + c * 32 + o);
        float w1 = __ldg(W3 + (size_t)(j0 + 1) * 512 + c * 32 + o);
        float w2 = __ldg(W3 + (size_t)(j0 + 2) * 512 + c * 32 + o);
        float w3 = __ldg(W3 + (size_t)(j0 + 3) * 512 + c * 32 + o);
#pragma unroll
        for (int m = 0; m < 8; m++) {
            float pm = sp[m][c];
            acc[m][0] = fmaf(pm, w0, acc[m][0]);
            acc[m][1] = fmaf(pm, w1, acc[m][1]);
            acc[m][2] = fmaf(pm, w2, acc[m][2]);
            acc[m][3] = fmaf(pm, w3, acc[m][3]);
        }
    }
    float c0 = ssc[j0], c1 = ssc[j0 + 1], c2 = ssc[j0 + 2], c3 = ssc[j0 + 3];
    float h0 = ssh[j0], h1 = ssh[j0 + 1], h2v = ssh[j0 + 2], h3 = ssh[j0 + 3];
    uint2* q2base = (uint2*)g_Q4;
#pragma unroll
    for (int m = 0; m < 8; m++) {
        __half2 p0 = __floats2half2_rn(acc[m][0] * c0, acc[m][1] * c1);
        __half2 p1 = __floats2half2_rn(acc[m][2] * c2, acc[m][3] * c3);
        uint2 u;
        u.x = *(const unsigned int*)&p0;
        u.y = *(const unsigned int*)&p1;
        size_t u2idx = (((size_t)(mg0 + m) * 4 + (jg >> 1)) * 32 + o) * 2 + (jg & 1);
        q2base[u2idx] = u;
        r16p[jg][m][o] = fmaf(h0, acc[m][0], fmaf(h1, acc[m][1], fmaf(h2v, acc[m][2], h3 * acc[m][3])));
    }
    __syncthreads();
    {
        int m = tid >> 5;
        float sum = 0.f;
#pragma unroll
        for (int g = 0; g < 8; g++) sum += r16p[g][m][o];
        float pb = 0.f;
#pragma unroll
        for (int c = 0; c < 16; c++) pb = fmaf(sp[m][c], __ldg(b3 + c * 32 + o), pb);
        g_Qb[(size_t)(mg0 + m) * 32 + o] = sum + pb;
    }
}

// ---------------- stage3: f32x2 packed accumulation ----------------
__global__ __launch_bounds__(256) void stage3_kernel(float* __restrict__ out) {
    __shared__ __align__(16) float2 sH[32 * 16];
    __shared__ int sidx[32];
    __shared__ float wmax[8][32];
    int tid = threadIdx.x;
    int q = blockIdx.x;
    size_t r0 = (size_t)q * KK;
    if (tid < 32) sidx[tid] = g_idx[r0 + tid];
    for (int t = tid; t < 512; t += 256) {
        int k = t >> 4, jp = t & 15;
        sH[k * 16 + jp] = ((const float2*)(g_h2 + (r0 + k) * 32))[jp];
    }
    __syncthreads();

    int w = tid >> 5, o = tid & 31, b = q >> 11;
    float vmax = -3.4e38f;
#pragma unroll
    for (int kk = 0; kk < 4; kk++) {
        int k = w + kk * 8;
        int m = sidx[k];
        size_t mg = ((size_t)(b << 11) + m);
        const uint4* Qp = g_Q4 + mg * QSTRIDE4 + o;
        const unsigned long long* sHk = (const unsigned long long*)&sH[k * 16];
        unsigned long long acc2 = pack2(__ldg(g_Qb + mg * 32 + o), 0.f);
#pragma unroll
        for (int jq = 0; jq < 4; jq++) {
            uint4 u = Qp[(size_t)jq * 32];
            float2 q0 = __half22float2(*(const __half2*)&u.x);
            float2 q1 = __half22float2(*(const __half2*)&u.y);
            float2 q2 = __half22float2(*(const __half2*)&u.z);
            float2 q3 = __half22float2(*(const __half2*)&u.w);
            acc2 = ffma2(sHk[jq * 4 + 0], pack2(q0.x, q0.y), acc2);
            acc2 = ffma2(sHk[jq * 4 + 1], pack2(q1.x, q1.y), acc2);
            acc2 = ffma2(sHk[jq * 4 + 2], pack2(q2.x, q2.y), acc2);
            acc2 = ffma2(sHk[jq * 4 + 3], pack2(q3.x, q3.y), acc2);
        }
        float2 a = unpack2(acc2);
        vmax = fmaxf(vmax, a.x + a.y);
    }
    wmax[w][o] = vmax;
    __syncthreads();
    if (tid < 32) {
        float v = wmax[0][tid];
#pragma unroll
        for (int i = 1; i < 8; i++) v = fmaxf(v, wmax[i][tid]);
        out[(size_t)q * 32 + tid] = v;
    }
}

// ---------------- statsC ----------------
__global__ __launch_bounds__(256) void statsC_kernel(const float* __restrict__ out) {
    int tid = threadIdx.x;
    int q = blockIdx.x * 256 + tid;
    float v[32], s2[32];
    const float4* p = (const float4*)(out + (size_t)q * 32);
#pragma unroll
    for (int i = 0; i < 8; i++) {
        float4 x = p[i];
        v[4 * i] = x.x; v[4 * i + 1] = x.y; v[4 * i + 2] = x.z; v[4 * i + 3] = x.w;
    }
#pragma unroll
    for (int c = 0; c < 32; c++) s2[c] = v[c] * v[c];
    int lane = tid & 31, w = tid >> 5;
    tr32(v, lane); tr32(s2, lane);
    __shared__ float red[2][8][32];
    red[0][w][lane] = v[0]; red[1][w][lane] = s2[0];
    __syncthreads();
    if (tid < 32) {
        float a = 0.f, a2 = 0.f;
#pragma unroll
        for (int ww = 0; ww < 8; ww++) { a += red[0][ww][tid]; a2 += red[1][ww][tid]; }
        g_ps [tid * 32 + blockIdx.x] = a;
        g_ps2[tid * 32 + blockIdx.x] = a2;
    }
}

// ---------------- finalbn: fused fin3 + normalize ----------------
__global__ __launch_bounds__(256) void finalbn_kernel(float* __restrict__ out,
                                                      const float* __restrict__ gbn,
                                                      const float* __restrict__ bbn) {
    __shared__ float ssc[32], ssh[32];
    int tid = threadIdx.x;
    if (tid < 32) {
        float s = 0.f, s2 = 0.f;
#pragma unroll
        for (int i = 0; i < 32; i++) {
            s  += g_ps [tid * 32 + i];
            s2 += g_ps2[tid * 32 + i];
        }
        const float invc = 1.f / (float)MTOT;
        float mean = s * invc;
        float var  = s2 * invc - mean * mean;
        float iv = rsqrtf(var + EPS);
        float sc = gbn[tid] * iv;
        ssc[tid] = sc;
        ssh[tid] = fmaf(-mean, sc, bbn[tid]);
    }
    __syncthreads();
    int e = blockIdx.x * 256 + tid;
    float4 v = ((float4*)out)[e];
    int c = (e * 4) & 31;
    v.x = fmaf(v.x, ssc[c],     ssh[c]);
    v.y = fmaf(v.y, ssc[c + 1], ssh[c + 1]);
    v.z = fmaf(v.z, ssc[c + 2], ssh[c + 2]);
    v.w = fmaf(v.w, ssc[c + 3], ssh[c + 3]);
    ((float4*)out)[e] = v;
}

// ---------------- launcher ----------------
extern "C" void kernel_launch(void* const* d_in, const int* in_sizes, int n_in,
                              void* d_out, int out_size) {
    const float* xyz    = (const float*)d_in[0];
    const float* points = (const float*)d_in[1];
    const float* W1     = (const float*)d_in[2];
    const float* b1     = (const float*)d_in[3];
    const float* g1     = (const float*)d_in[4];
    const float* be1    = (const float*)d_in[5];
    const float* W2     = (const float*)d_in[6];
    const float* b2     = (const float*)d_in[7];
    const float* g2     = (const float*)d_in[8];
    const float* be2    = (const float*)d_in[9];
    const float* W3     = (const float*)d_in[10];
    const float* b3     = (const float*)d_in[11];
    const float* gbn    = (const float*)d_in[12];
    const float* bbn    = (const float*)d_in[13];
    float* out = (float*)d_out;

    float* p_sc2; cudaGetSymbolAddress((void**)&p_sc2, g_sc2);

    knn_kernel    <<<1024, 256>>>(xyz, W1, b1);
    fin1_kernel   <<<1, 1024>>>(g1, be1, W2, b2, W1, b1);
    stage2_kernel <<<512, 256>>>();
    fin_kernel    <<<1, 1024>>>(512, 1.f / (float)RTOT, g2, be2, p_sc2);
    qcompute_kernel<<<MTOT / 8, 256>>>(points, W3, b3);
    stage3_kernel <<<MTOT, 256>>>(out);
    statsC_kernel <<<32, 256>>>(out);
    finalbn_kernel<<<256, 256>>>(out, gbn, bbn);
}

// round 16
// speedup vs baseline: 1.1057x; 1.0158x over previous
#include <cuda_runtime.h>
#include <cuda_fp16.h>
#include <cstdint>

#define BB 4
#define NN 2048
#define KK 32
#define CIN 16
#define COUT 32
#define HH 32
#define RTOT (BB*NN*KK)      // 262144
#define MTOT (BB*NN)         // 8192
#define EPS 1e-5f
#define FULLMASK 0xffffffffu

// Q layout: [m][jq=0..3][o] as uint4 (4 half2 = 8 j's). Coalesced per warp (lane=o).
#define QSTRIDE4 (4*32)

// ---------------- scratch ----------------
__device__ __align__(16) float g_h2[(size_t)RTOT*HH];       // 32 MB (pre-BN2 h2)
__device__ __align__(16) uint4 g_Q4[(size_t)MTOT*QSTRIDE4]; // 16.8 MB fp16 Q tiles (UNscaled)
__device__ __align__(16) float g_Qb[(size_t)MTOT*COUT];     // 1 MB pb3 per (m,o)
__device__ __align__(16) float4 g_rel[RTOT];                // 4 MB rel coords
__device__ int g_idx[RTOT];
__device__ __align__(16) float g_ps [32*1024];
__device__ __align__(16) float g_ps2[32*1024];
__device__ float g_sc2[64];
__device__ __align__(16) float g_W2f[1024];   // sc1-folded W2
__device__ float g_b2f[32];                   // sh1-folded b2
__device__ float cW1x[32], cW1y[32], cW1z[32], cB1[32];

// ---------------- helpers ----------------
__device__ __forceinline__ unsigned long long pack2(float x, float y) {
    unsigned long long r;
    asm("mov.b64 %0, {%1,%2};" : "=l"(r) : "f"(x), "f"(y));
    return r;
}
__device__ __forceinline__ float2 unpack2(unsigned long long v) {
    float2 r;
    asm("mov.b64 {%0,%1}, %2;" : "=f"(r.x), "=f"(r.y) : "l"(v));
    return r;
}
__device__ __forceinline__ unsigned long long ffma2(unsigned long long a, unsigned long long b, unsigned long long c) {
    unsigned long long d;
    asm("fma.rn.f32x2 %0, %1, %2, %3;" : "=l"(d) : "l"(a), "l"(b), "l"(c));
    return d;
}

// warp transpose-reduce
__device__ __forceinline__ void tr32(float (&acc)[32], int lane) {
#pragma unroll
    for (int s = 16; s >= 1; s >>= 1) {
#pragma unroll
        for (int i = 0; i < s; i++) {
            float a0 = acc[i], a1 = acc[i + s];
            float give = (lane & s) ? a0 : a1;
            float keep = (lane & s) ? a1 : a0;
            acc[i] = keep + __shfl_xor_sync(FULLMASK, give, s);
        }
    }
}

// ---------------- KNN + rel + h1 stats ----------------
__device__ __forceinline__ void cas_pair(float& d, int& i, int stride, bool up, int lane) {
    float od = __shfl_xor_sync(FULLMASK, d, stride);
    int   oi = __shfl_xor_sync(FULLMASK, i, stride);
    bool otherSmaller = (od < d) || (od == d && oi < i);
    bool lower = ((lane & stride) == 0);
    bool take = (lower == up) ? otherSmaller : !otherSmaller;
    if (take) { d = od; i = oi; }
}
__device__ __forceinline__ void sort32(float& d, int& i, bool asc, int lane) {
#pragma unroll
    for (int k = 2; k <= 32; k <<= 1) {
        bool up = (((lane & k) == 0) == asc);
#pragma unroll
        for (int s = k >> 1; s > 0; s >>= 1) cas_pair(d, i, s, up, lane);
    }
}
__device__ __forceinline__ void merge32(float& d, int& i, int lane) {
#pragma unroll
    for (int s = 16; s > 0; s >>= 1) cas_pair(d, i, s, true, lane);
}

__global__ __launch_bounds__(256) void knn_kernel(const float* __restrict__ xyz,
                                                  const float* __restrict__ W1,
                                                  const float* __restrict__ b1) {
    __shared__ float4 sp4[NN];
    __shared__ float red[2][8][32];
    __shared__ float sW1[96], sb1s[32];
    int b = blockIdx.x >> 8;
    int nbase = (blockIdx.x & 255) * 8;
    int tid = threadIdx.x;
    if (tid < 96) sW1[tid] = W1[tid];
    else if (tid < 128) sb1s[tid - 96] = b1[tid - 96];
    for (int i = tid; i < NN; i += 256) {
        const float* p = xyz + ((size_t)b * NN + i) * 3;
        float x = p[0], y = p[1], z = p[2];
        sp4[i] = make_float4(x, y, z, x * x + y * y + z * z);
    }
    __syncthreads();
    int w = tid >> 5, lane = tid & 31;
    int n = nbase + w;
    float4 qp = sp4[n];

    float4 tA = sp4[lane];
    float4 tB = sp4[32 + lane];
    float d = fmaf(-2.f, qp.x * tA.x + qp.y * tA.y + qp.z * tA.z, qp.w + tA.w);
    int di = lane;
    float e = fmaf(-2.f, qp.x * tB.x + qp.y * tB.y + qp.z * tB.z, qp.w + tB.w);
    int ei = 32 + lane;
    sort32(d, di, true, lane);
    sort32(e, ei, false, lane);
    bool takeE = (e < d) || (e == d && ei < di);
    if (takeE) { d = e; di = ei; }
    merge32(d, di, lane);
    float kmax = __shfl_sync(FULLMASK, d, 31);

    for (int c = 1; c < 32; c++) {
        int j = c * 64 + lane;
        float4 t0 = sp4[j];
        float4 t1 = sp4[j + 32];
        float cd0 = fmaf(-2.f, qp.x * t0.x + qp.y * t0.y + qp.z * t0.z, qp.w + t0.w);
        float cd1 = fmaf(-2.f, qp.x * t1.x + qp.y * t1.y + qp.z * t1.z, qp.w + t1.w);
        unsigned m0 = __ballot_sync(FULLMASK, cd0 < kmax);
        while (m0) {
            int src = __ffs(m0) - 1;
            m0 &= m0 - 1;
            float v = __shfl_sync(FULLMASK, cd0, src);
            if (v >= kmax) continue;
            int vi = j - lane + src;
            unsigned le = __ballot_sync(FULLMASK, d <= v);
            int pos = __popc(le);
            float ds = __shfl_up_sync(FULLMASK, d, 1);
            int   is = __shfl_up_sync(FULLMASK, di, 1);
            if (lane == pos)      { d = v;  di = vi; }
            else if (lane > pos)  { d = ds; di = is; }
            kmax = __shfl_sync(FULLMASK, d, 31);
        }
        unsigned m1 = __ballot_sync(FULLMASK, cd1 < kmax);
        while (m1) {
            int src = __ffs(m1) - 1;
            m1 &= m1 - 1;
            float v = __shfl_sync(FULLMASK, cd1, src);
            if (v >= kmax) continue;
            int vi = j - lane + 32 + src;
            unsigned le = __ballot_sync(FULLMASK, d <= v);
            int pos = __popc(le);
            float ds = __shfl_up_sync(FULLMASK, d, 1);
            int   is = __shfl_up_sync(FULLMASK, di, 1);
            if (lane == pos)      { d = v;  di = vi; }
            else if (lane > pos)  { d = ds; di = is; }
            kmax = __shfl_sync(FULLMASK, d, 31);
        }
    }
    size_t r = ((size_t)b * NN + n) * KK + lane;
    g_idx[r] = di;

    float4 tn = sp4[di];
    float rx = tn.x - qp.x, ry = tn.y - qp.y, rz = tn.z - qp.z;
    g_rel[r] = make_float4(rx, ry, rz, 0.f);

    float s[32];
#pragma unroll
    for (int c = 0; c < 32; c++)
        s[c] = fmaxf(fmaf(rx, sW1[c], fmaf(ry, sW1[32 + c], fmaf(rz, sW1[64 + c], sb1s[c]))), 0.f);
    tr32(s, lane);
    red[0][w][lane] = s[0];
    float s2[32];
#pragma unroll
    for (int c = 0; c < 32; c++) {
        float v = fmaxf(fmaf(rx, sW1[c], fmaf(ry, sW1[32 + c], fmaf(rz, sW1[64 + c], sb1s[c]))), 0.f);
        s2[c] = v * v;
    }
    tr32(s2, lane);
    red[1][w][lane] = s2[0];
    __syncthreads();
    if (tid < 32) {
        float a = 0.f, a2 = 0.f;
#pragma unroll
        for (int ww = 0; ww < 8; ww++) { a += red[0][ww][tid]; a2 += red[1][ww][tid]; }
        g_ps [tid * 1024 + blockIdx.x] = a;
        g_ps2[tid * 1024 + blockIdx.x] = a2;
    }
}

// ---------------- fin1 (+prep): BN1 folded into W2f/b2f ----------------
__global__ __launch_bounds__(1024) void fin1_kernel(const float* __restrict__ g1,
                                                    const float* __restrict__ be1,
                                                    const float* __restrict__ W2,
                                                    const float* __restrict__ b2,
                                                    const float* __restrict__ W1,
                                                    const float* __restrict__ b1) {
    __shared__ float ssc[32], ssh[32];
    int tid = threadIdx.x, w = tid >> 5, l = tid & 31;
    if (tid < 32) { cW1x[tid] = W1[tid]; cW1y[tid] = W1[32 + tid]; cW1z[tid] = W1[64 + tid]; cB1[tid] = b1[tid]; }
    const float4* P  = (const float4*)(g_ps  + w * 1024);
    const float4* P2 = (const float4*)(g_ps2 + w * 1024);
    float s = 0.f, s2 = 0.f;
#pragma unroll
    for (int it = 0; it < 8; it++) {
        float4 a = P[it * 32 + l];
        float4 c = P2[it * 32 + l];
        s  += (a.x + a.y) + (a.z + a.w);
        s2 += (c.x + c.y) + (c.z + c.w);
    }
#pragma unroll
    for (int o = 16; o >= 1; o >>= 1) {
        s  += __shfl_down_sync(FULLMASK, s, o);
        s2 += __shfl_down_sync(FULLMASK, s2, o);
    }
    if (l == 0) {
        const float invc = 1.f / (float)RTOT;
        float mean = s * invc;
        float var  = s2 * invc - mean * mean;
        float iv = rsqrtf(var + EPS);
        float sc = g1[w] * iv;
        ssc[w] = sc;
        ssh[w] = fmaf(-mean, sc, be1[w]);
    }
    __syncthreads();
    g_W2f[tid] = ssc[tid >> 5] * W2[tid];
    float v = ssh[l] * W2[l * 32 + w];
#pragma unroll
    for (int o = 16; o >= 1; o >>= 1) v += __shfl_down_sync(FULLMASK, v, o);
    if (l == 0) g_b2f[w] = b2[w] + v;
}

// ---------------- stage2: 2 rows/thread; W2 rows via LDS.128 ----------------
__global__ __launch_bounds__(256) void stage2_kernel() {
    __shared__ __align__(16) float sW2f[1024];
    __shared__ float sb2f[32];
    __shared__ float sW1x[32], sW1y[32], sW1z[32], sB1[32];
    __shared__ float red[2][8][32];
    int tid = threadIdx.x;
    ((float4*)sW2f)[tid] = ((const float4*)g_W2f)[tid & 255];
    if (tid < 32) {
        sb2f[tid] = g_b2f[tid];
        sW1x[tid] = cW1x[tid]; sW1y[tid] = cW1y[tid];
        sW1z[tid] = cW1z[tid]; sB1[tid]  = cB1[tid];
    }
    __syncthreads();

    int rA = blockIdx.x * 256 + tid;
    int rB = rA + 131072;
    float4 relA = g_rel[rA];
    float4 relB = g_rel[rB];

    unsigned long long accA[16], accB[16];
#pragma unroll
    for (int q = 0; q < 16; q++) {
        unsigned long long bb = pack2(sb2f[2 * q], sb2f[2 * q + 1]);
        accA[q] = bb; accB[q] = bb;
    }
    const ulonglong2* w2p = (const ulonglong2*)sW2f;
#pragma unroll
    for (int j = 0; j < 32; j++) {
        float hA = fmaxf(fmaf(relA.x, sW1x[j], fmaf(relA.y, sW1y[j], fmaf(relA.z, sW1z[j], sB1[j]))), 0.f);
        float hB = fmaxf(fmaf(relB.x, sW1x[j], fmaf(relB.y, sW1y[j], fmaf(relB.z, sW1z[j], sB1[j]))), 0.f);
        unsigned long long hvA = pack2(hA, hA);
        unsigned long long hvB = pack2(hB, hB);
        const ulonglong2* row = w2p + j * 8;
#pragma unroll
        for (int q = 0; q < 8; q++) {
            ulonglong2 wv = row[q];
            accA[2 * q]     = ffma2(hvA, wv.x, accA[2 * q]);
            accA[2 * q + 1] = ffma2(hvA, wv.y, accA[2 * q + 1]);
            accB[2 * q]     = ffma2(hvB, wv.x, accB[2 * q]);
            accB[2 * q + 1] = ffma2(hvB, wv.y, accB[2 * q + 1]);
        }
    }

    float vA[32], vB[32];
#pragma unroll
    for (int q = 0; q < 16; q++) {
        float2 pA = unpack2(accA[q]);
        float2 pB = unpack2(accB[q]);
        vA[2 * q] = fmaxf(pA.x, 0.f); vA[2 * q + 1] = fmaxf(pA.y, 0.f);
        vB[2 * q] = fmaxf(pB.x, 0.f); vB[2 * q + 1] = fmaxf(pB.y, 0.f);
    }
    float4* oA = (float4*)(g_h2 + (size_t)rA * 32);
    float4* oB = (float4*)(g_h2 + (size_t)rB * 32);
#pragma unroll
    for (int q = 0; q < 8; q++) {
        oA[q] = make_float4(vA[4 * q], vA[4 * q + 1], vA[4 * q + 2], vA[4 * q + 3]);
        oB[q] = make_float4(vB[4 * q], vB[4 * q + 1], vB[4 * q + 2], vB[4 * q + 3]);
    }

    float s[32], s2[32];
#pragma unroll
    for (int c = 0; c < 32; c++) {
        s[c]  = vA[c] + vB[c];
        s2[c] = fmaf(vA[c], vA[c], vB[c] * vB[c]);
    }
    int lane = tid & 31, w = tid >> 5;
    tr32(s, lane); tr32(s2, lane);
    red[0][w][lane] = s[0]; red[1][w][lane] = s2[0];
    __syncthreads();
    if (tid < 32) {
        float a = 0.f, a2 = 0.f;
#pragma unroll
        for (int ww = 0; ww < 8; ww++) { a += red[0][ww][tid]; a2 += red[1][ww][tid]; }
        g_ps [tid * 512 + blockIdx.x] = a;
        g_ps2[tid * 512 + blockIdx.x] = a2;
    }
}

// ---------------- qcompute: unscaled Q + pb3; block 1024 computes sc2 (fin2) ----------------
__global__ __launch_bounds__(256) void qcompute_kernel(const float* __restrict__ points,
                                                       const float* __restrict__ W3,
                                                       const float* __restrict__ b3,
                                                       const float* __restrict__ g2,
                                                       const float* __restrict__ be2) {
    int tid = threadIdx.x;
    if (blockIdx.x == 1024) {
        // fin2 branch: reduce stage2 partials -> g_sc2 (independent of qcompute main)
        int lane = tid & 31, w = tid >> 5;
#pragma unroll
        for (int cc = 0; cc < 4; cc++) {
            int c = w * 4 + cc;
            float a = 0.f, a2 = 0.f;
            const float4* P  = (const float4*)(g_ps  + c * 512);
            const float4* P2 = (const float4*)(g_ps2 + c * 512);
#pragma unroll
            for (int i = 0; i < 4; i++) {
                float4 x = P[i * 32 + lane];
                float4 y = P2[i * 32 + lane];
                a  += (x.x + x.y) + (x.z + x.w);
                a2 += (y.x + y.y) + (y.z + y.w);
            }
#pragma unroll
            for (int o = 16; o >= 1; o >>= 1) {
                a  += __shfl_down_sync(FULLMASK, a, o);
                a2 += __shfl_down_sync(FULLMASK, a2, o);
            }
            if (lane == 0) {
                const float invc = 1.f / (float)RTOT;
                float mean = a * invc;
                float var  = a2 * invc - mean * mean;
                float iv = rsqrtf(var + EPS);
                float sc = g2[c] * iv;
                g_sc2[c]      = sc;
                g_sc2[32 + c] = fmaf(-mean, sc, be2[c]);
            }
        }
        return;
    }

    __shared__ float sp[8][16];
    int mg0 = blockIdx.x * 8;
    if (tid < 128) sp[tid >> 4][tid & 15] = points[(size_t)(mg0 + (tid >> 4)) * CIN + (tid & 15)];
    __syncthreads();

    int o = tid & 31, jg = tid >> 5, j0 = jg * 4;
    float acc[8][4];
#pragma unroll
    for (int m = 0; m < 8; m++)
#pragma unroll
        for (int jj = 0; jj < 4; jj++) acc[m][jj] = 0.f;

#pragma unroll
    for (int c = 0; c < 16; c++) {
        float w0 = __ldg(W3 + (size_t)(j0 + 0) * 512 + c * 32 + o);
        float w1 = __ldg(W3 + (size_t)(j0 + 1) * 512 + c * 32 + o);
        float w2 = __ldg(W3 + (size_t)(j0 + 2) * 512 + c * 32 + o);
        float w3 = __ldg(W3 + (size_t)(j0 + 3) * 512 + c * 32 + o);
#pragma unroll
        for (int m = 0; m < 8; m++) {
            float pm = sp[m][c];
            acc[m][0] = fmaf(pm, w0, acc[m][0]);
            acc[m][1] = fmaf(pm, w1, acc[m][1]);
            acc[m][2] = fmaf(pm, w2, acc[m][2]);
            acc[m][3] = fmaf(pm, w3, acc[m][3]);
        }
    }
    uint2* q2base = (uint2*)g_Q4;
#pragma unroll
    for (int m = 0; m < 8; m++) {
        __half2 p0 = __floats2half2_rn(acc[m][0], acc[m][1]);
        __half2 p1 = __floats2half2_rn(acc[m][2], acc[m][3]);
        uint2 u;
        u.x = *(const unsigned int*)&p0;
        u.y = *(const unsigned int*)&p1;
        size_t u2idx = (((size_t)(mg0 + m) * 4 + (jg >> 1)) * 32 + o) * 2 + (jg & 1);
        q2base[u2idx] = u;
    }
    {
        int m = tid >> 5;
        float pb = 0.f;
#pragma unroll
        for (int c = 0; c < 16; c++) pb = fmaf(sp[m][c], __ldg(b3 + c * 32 + o), pb);
        g_Qb[(size_t)(mg0 + m) * 32 + o] = pb;
    }
}

// ---------------- stage3: BN2 on sH load; f32x2 packed accumulation ----------------
__global__ __launch_bounds__(256) void stage3_kernel(float* __restrict__ out) {
    __shared__ __align__(16) float2 sH[32 * 16];
    __shared__ int sidx[32];
    __shared__ float wmax[8][32];
    __shared__ float sbn[64];
    int tid = threadIdx.x;
    int q = blockIdx.x;
    size_t r0 = (size_t)q * KK;
    if (tid < 32) sidx[tid] = g_idx[r0 + tid];
    else if (tid >= 64 && tid < 128) sbn[tid - 64] = g_sc2[tid - 64];
    __syncthreads();
    for (int t = tid; t < 512; t += 256) {
        int k = t >> 4, jp = t & 15;
        float2 h = ((const float2*)(g_h2 + (r0 + k) * 32))[jp];
        int j = jp * 2;
        sH[k * 16 + jp] = make_float2(fmaf(h.x, sbn[j],     sbn[32 + j]),
                                      fmaf(h.y, sbn[j + 1], sbn[33 + j]));
    }
    __syncthreads();

    int w = tid >> 5, o = tid & 31, b = q >> 11;
    float vmax = -3.4e38f;
#pragma unroll
    for (int kk = 0; kk < 4; kk++) {
        int k = w + kk * 8;
        int m = sidx[k];
        size_t mg = ((size_t)(b << 11) + m);
        const uint4* Qp = g_Q4 + mg * QSTRIDE4 + o;
        const unsigned long long* sHk = (const unsigned long long*)&sH[k * 16];
        unsigned long long acc2 = pack2(__ldg(g_Qb + mg * 32 + o), 0.f);
#pragma unroll
        for (int jq = 0; jq < 4; jq++) {
            uint4 u = Qp[(size_t)jq * 32];
            float2 q0 = __half22float2(*(const __half2*)&u.x);
            float2 q1 = __half22float2(*(const __half2*)&u.y);
            float2 q2 = __half22float2(*(const __half2*)&u.z);
            float2 q3 = __half22float2(*(const __half2*)&u.w);
            acc2 = ffma2(sHk[jq * 4 + 0], pack2(q0.x, q0.y), acc2);
            acc2 = ffma2(sHk[jq * 4 + 1], pack2(q1.x, q1.y), acc2);
            acc2 = ffma2(sHk[jq * 4 + 2], pack2(q2.x, q2.y), acc2);
            acc2 = ffma2(sHk[jq * 4 + 3], pack2(q3.x, q3.y), acc2);
        }
        float2 a = unpack2(acc2);
        vmax = fmaxf(vmax, a.x + a.y);
    }
    wmax[w][o] = vmax;
    __syncthreads();
    if (tid < 32) {
        float v = wmax[0][tid];
#pragma unroll
        for (int i = 1; i < 8; i++) v = fmaxf(v, wmax[i][tid]);
        out[(size_t)q * 32 + tid] = v;
    }
}

// ---------------- statsC ----------------
__global__ __launch_bounds__(256) void statsC_kernel(const float* __restrict__ out) {
    int tid = threadIdx.x;
    int q = blockIdx.x * 256 + tid;
    float v[32], s2[32];
    const float4* p = (const float4*)(out + (size_t)q * 32);
#pragma unroll
    for (int i = 0; i < 8; i++) {
        float4 x = p[i];
        v[4 * i] = x.x; v[4 * i + 1] = x.y; v[4 * i + 2] = x.z; v[4 * i + 3] = x.w;
    }
#pragma unroll
    for (int c = 0; c < 32; c++) s2[c] = v[c] * v[c];
    int lane = tid & 31, w = tid >> 5;
    tr32(v, lane); tr32(s2, lane);
    __shared__ float red[2][8][32];
    red[0][w][lane] = v[0]; red[1][w][lane] = s2[0];
    __syncthreads();
    if (tid < 32) {
        float a = 0.f, a2 = 0.f;
#pragma unroll
        for (int ww = 0; ww < 8; ww++) { a += red[0][ww][tid]; a2 += red[1][ww][tid]; }
        g_ps [tid * 32 + blockIdx.x] = a;
        g_ps2[tid * 32 + blockIdx.x] = a2;
    }
}

// ---------------- finalbn: fused fin3 + normalize ----------------
__global__ __launch_bounds__(256) void finalbn_kernel(float* __restrict__ out,
                                                      const float* __restrict__ gbn,
                                                      const float* __restrict__ bbn) {
    __shared__ float ssc[32], ssh[32];
    int tid = threadIdx.x;
    if (tid < 32) {
        float s = 0.f, s2 = 0.f;
#pragma unroll
        for (int i = 0; i < 32; i++) {
            s  += g_ps [tid * 32 + i];
            s2 += g_ps2[tid * 32 + i];
        }
        const float invc = 1.f / (float)MTOT;
        float mean = s * invc;
        float var  = s2 * invc - mean * mean;
        float iv = rsqrtf(var + EPS);
        float sc = gbn[tid] * iv;
        ssc[tid] = sc;
        ssh[tid] = fmaf(-mean, sc, bbn[tid]);
    }
    __syncthreads();
    int e = blockIdx.x * 256 + tid;
    float4 v = ((float4*)out)[e];
    int c = (e * 4) & 31;
    v.x = fmaf(v.x, ssc[c],     ssh[c]);
    v.y = fmaf(v.y, ssc[c + 1], ssh[c + 1]);
    v.z = fmaf(v.z, ssc[c + 2], ssh[c + 2]);
    v.w = fmaf(v.w, ssc[c + 3], ssh[c + 3]);
    ((float4*)out)[e] = v;
}

// ---------------- launcher ----------------
extern "C" void kernel_launch(void* const* d_in, const int* in_sizes, int n_in,
                              void* d_out, int out_size) {
    const float* xyz    = (const float*)d_in[0];
    const float* points = (const float*)d_in[1];
    const float* W1     = (const float*)d_in[2];
    const float* b1     = (const float*)d_in[3];
    const float* g1     = (const float*)d_in[4];
    const float* be1    = (const float*)d_in[5];
    const float* W2     = (const float*)d_in[6];
    const float* b2     = (const float*)d_in[7];
    const float* g2     = (const float*)d_in[8];
    const float* be2    = (const float*)d_in[9];
    const float* W3     = (const float*)d_in[10];
    const float* b3     = (const float*)d_in[11];
    const float* gbn    = (const float*)d_in[12];
    const float* bbn    = (const float*)d_in[13];
    float* out = (float*)d_out;

    knn_kernel    <<<1024, 256>>>(xyz, W1, b1);
    fin1_kernel   <<<1, 1024>>>(g1, be1, W2, b2, W1, b1);
    stage2_kernel <<<512, 256>>>();
    qcompute_kernel<<<1025, 256>>>(points, W3, b3, g2, be2);
    stage3_kernel <<<MTOT, 256>>>(out);
    statsC_kernel <<<32, 256>>>(out);
    finalbn_kernel<<<256, 256>>>(out, gbn, bbn);
}